// round 9
// baseline (speedup 1.0000x reference)
#include <cuda_runtime.h>
#include <math.h>

#define DDIM  2048
#define NEXP  64
#define NOUT  128
#define TOPK  8

#define BM 64
#define BN 128      // 64 gate cols + 64 noise cols
#define BK 32
#define NT 256
#define NCHUNK (DDIM / BK)   // 64

#define GAP_THETA 1e-4f

// smem: double-buffered As[32][64] + Bs[32][128] = 2*(2048+4096) floats = 48KB
#define BUFSTRIDE 6144

// ---- f32x2 packed helpers --------------------------------------------------
__device__ __forceinline__ unsigned long long dup2(float x) {
    unsigned long long d; unsigned int u = __float_as_uint(x);
    asm("mov.b64 %0, {%1, %1};" : "=l"(d) : "r"(u));
    return d;
}
__device__ __forceinline__ void ffma2(unsigned long long& d,
                                      unsigned long long a, unsigned long long b) {
    asm("fma.rn.f32x2 %0, %1, %2, %0;" : "+l"(d) : "l"(a), "l"(b));
}
__device__ __forceinline__ unsigned long long fmul2(unsigned long long a,
                                                    unsigned long long b) {
    unsigned long long d;
    asm("mul.rn.f32x2 %0, %1, %2;" : "=l"(d) : "l"(a), "l"(b));
    return d;
}
__device__ __forceinline__ unsigned long long fadd2(unsigned long long a,
                                                    unsigned long long b) {
    unsigned long long d;
    asm("add.rn.f32x2 %0, %1, %2;" : "=l"(d) : "l"(a), "l"(b));
    return d;
}
__device__ __forceinline__ unsigned long long ffma2o(unsigned long long a,
                                                     unsigned long long b,
                                                     unsigned long long c) {
    unsigned long long d;
    asm("fma.rn.f32x2 %0, %1, %2, %3;" : "=l"(d) : "l"(a), "l"(b), "l"(c));
    return d;
}
__device__ __forceinline__ void unpack2(unsigned long long v, float& lo, float& hi) {
    unsigned int a, b;
    asm("mov.b64 {%0, %1}, %2;" : "=r"(a), "=r"(b) : "l"(v));
    lo = __uint_as_float(a); hi = __uint_as_float(b);
}

__device__ __forceinline__ float softplus_f(float x) {
    return fmaxf(x, 0.f) + log1pf(expf(-fabsf(x)));
}
__device__ __forceinline__ double softplus_d(double x) {
    return fmax(x, 0.0) + log1p(exp(-fabs(x)));
}

// ---------------------------------------------------------------------------
// Fused router: dual GEMM + in-block softmax/top-k epilogue.
// Block: 256 threads, 64 tokens x 128 outputs. Grid: M/64 = 256 blocks.
// 2 CTAs resident per SM (48KB smem, <=128 regs) for latency hiding.
// ---------------------------------------------------------------------------
__global__ __launch_bounds__(NT, 2) void router_fused(
    const float* __restrict__ A,     // [M][DDIM]
    const float* __restrict__ Wg,    // [64][DDIM]
    const float* __restrict__ Wn,    // [64][DDIM]
    const float* __restrict__ noise, // [M][64]
    float* __restrict__ out,
    int M)
{
    extern __shared__ float sm[];

    const int tid = threadIdx.x;
    const int tx = tid & 31;          // col group (4 cols)
    const int ty = tid >> 5;          // row group (8 rows) == warp id (0..7)
    const int m0 = blockIdx.x * BM;

    // A loader: 8 floats of one m-row (k-subrange of 8)
    const int ar  = tid >> 2;         // 0..63
    const int ag  = tid & 3;          // k-group of 8: [8*ag, 8*ag+8)
    const int asw = ar ^ (8 * ag);    // swizzled col, conflict-free STS
    // B loader: 16 floats of one n-row (k-subrange of 16)
    const int br  = tid >> 1;         // 0..127
    const int bg  = tid & 1;          // k-half: [16*bg, 16*bg+16)
    const int bsw = br ^ (16 * bg);   // base swizzle (further ^8 per k-octet)

    const float* Aptr = A + (size_t)(m0 + ar) * DDIM + ag * 8;
    const float* Bptr = ((br < 64) ? (Wg + (size_t)br * DDIM)
                                   : (Wn + (size_t)(br - 64) * DDIM)) + bg * 16;

    const unsigned long long NEG1 =
        ((unsigned long long)0xBF800000u << 32) | 0xBF800000u;   // (-1,-1)

    unsigned long long s2[16], comp[16];
#pragma unroll
    for (int i = 0; i < 16; i++) { s2[i] = 0ull; comp[i] = 0ull; }

    // prefetch chunk 0
    float4 pa0 = *(const float4*)(Aptr + 0);
    float4 pa1 = *(const float4*)(Aptr + 4);
    float4 pb[4];
#pragma unroll
    for (int q = 0; q < 4; q++) pb[q] = *(const float4*)(Bptr + 4 * q);

    for (int c = 0; c < NCHUNK; c++) {
        float* As = sm + (c & 1) * BUFSTRIDE;
        float* Bs = As + 2048;

        // ---- stage chunk c (regs -> smem), swizzled, conflict-free
        {
            float va[8] = { pa0.x, pa0.y, pa0.z, pa0.w, pa1.x, pa1.y, pa1.z, pa1.w };
#pragma unroll
            for (int q = 0; q < 8; q++)
                As[(ag * 8 + q) * 64 + asw] = va[q];

            float vb[16] = { pb[0].x, pb[0].y, pb[0].z, pb[0].w,
                             pb[1].x, pb[1].y, pb[1].z, pb[1].w,
                             pb[2].x, pb[2].y, pb[2].z, pb[2].w,
                             pb[3].x, pb[3].y, pb[3].z, pb[3].w };
#pragma unroll
            for (int q = 0; q < 16; q++)
                Bs[(bg * 16 + q) * 128 + (bsw ^ (8 * (q >> 3)))] = vb[q];
        }
        __syncthreads();

        // ---- prefetch chunk c+1 (covered by compute below)
        if (c + 1 < NCHUNK) {
            const float* ap = Aptr + (c + 1) * BK;
            const float* bp = Bptr + (c + 1) * BK;
            pa0 = *(const float4*)(ap + 0);
            pa1 = *(const float4*)(ap + 4);
#pragma unroll
            for (int q = 0; q < 4; q++) pb[q] = *(const float4*)(bp + 4 * q);
        }

        // ---- compute chunk: 32 k-steps, 16 packed FFMA2 each
        unsigned long long c2[16];
#pragma unroll
        for (int g4 = 0; g4 < 4; g4++) {
            const float* Arow = As + ((ty ^ g4) * 8);
            const float* Brow = Bs + (((tx >> 1) ^ g4) * 8 + (tx & 1) * 4);
#pragma unroll
            for (int q = 0; q < 8; q++) {
                const int kk = g4 * 8 + q;
                ulonglong2 aA = *(const ulonglong2*)(Arow + kk * 64);
                ulonglong2 aB = *(const ulonglong2*)(Arow + kk * 64 + 4);
                unsigned long long ap4[4] = { aA.x, aA.y, aB.x, aB.y };
                float4 bf = *(const float4*)(Brow + kk * 128);
                unsigned long long b4[4] = { dup2(bf.x), dup2(bf.y), dup2(bf.z), dup2(bf.w) };
                if (g4 == 0 && q == 0) {
#pragma unroll
                    for (int p = 0; p < 4; p++)
#pragma unroll
                        for (int j = 0; j < 4; j++)
                            c2[p * 4 + j] = fmul2(ap4[p], b4[j]);
                } else {
#pragma unroll
                    for (int p = 0; p < 4; p++)
#pragma unroll
                        for (int j = 0; j < 4; j++)
                            ffma2(c2[p * 4 + j], ap4[p], b4[j]);
                }
            }
        }

        // ---- packed Kahan fold into masters
#pragma unroll
        for (int i = 0; i < 16; i++) {
            unsigned long long y  = ffma2o(NEG1, comp[i], c2[i]);   // x - comp
            unsigned long long t  = fadd2(s2[i], y);                // s + y
            unsigned long long df = ffma2o(NEG1, s2[i], t);         // t - s
            comp[i] = ffma2o(NEG1, y, df);                          // (t-s) - y
            s2[i] = t;
        }
    }

    // ---- dump logits to smem (reuse buffers as Ls[64][128] = 32KB)
    __syncthreads();
    float* Ls = sm;
#pragma unroll
    for (int p = 0; p < 4; p++)
#pragma unroll
        for (int j = 0; j < 4; j++) {
            float lo, hi;
            unpack2(s2[p * 4 + j], lo, hi);
            Ls[(ty * 8 + 2 * p + 0) * 128 + tx * 4 + j] = lo;
            Ls[(ty * 8 + 2 * p + 1) * 128 + tx * 4 + j] = hi;
        }
    __syncthreads();

    // ---- epilogue: each of the 8 warps handles 8 tokens
    const int lane = tid & 31;
    const int e0 = lane, e1 = lane + 32;

    for (int t8 = 0; t8 < 8; t8++) {
        const int ml = ty * 8 + t8;           // local token (0..63)
        const int m  = m0 + ml;               // global token
        const float* L = Ls + ml * 128;
        const float* NZ = noise + (size_t)m * NEXP;

        float gl0 = L[e0],      gl1 = L[e1];
        float nl0 = L[64 + e0], nl1 = L[64 + e1];
        float nz0 = NZ[e0],     nz1 = NZ[e1];

        float l0 = fmaf(nz0, softplus_f(nl0), gl0);
        float l1 = fmaf(nz1, softplus_f(nl1), gl1);

        // softmax over 64
        float mx = fmaxf(l0, l1);
#pragma unroll
        for (int off = 16; off > 0; off >>= 1)
            mx = fmaxf(mx, __shfl_xor_sync(0xffffffffu, mx, off));
        float ex0 = expf(l0 - mx), ex1 = expf(l1 - mx);
        float ssum = ex0 + ex1;
#pragma unroll
        for (int off = 16; off > 0; off >>= 1)
            ssum += __shfl_xor_sync(0xffffffffu, ssum, off);
        float inv = 1.0f / ssum;
        float g0 = ex0 * inv, g1 = ex1 * inv;

        float* gates_out = out + (size_t)M * (2 * TOPK) + (size_t)m * NEXP;
        gates_out[e0] = g0;
        gates_out[e1] = g1;

        float* vals_out = out + (size_t)m * TOPK;
        float* inds_out = out + (size_t)M * TOPK + (size_t)m * TOPK;

        // fast top-9 scan with min-adjacent-gap certificate
        float c0 = l0, c1 = l1;
        int   top_i[TOPK];
        float top_v[TOPK];
        float prev = 0.f, mingap = 1e30f;

#pragma unroll
        for (int t = 0; t < TOPK + 1; t++) {
            float bv; int bi;
            if (c0 >= c1) { bv = c0; bi = e0; } else { bv = c1; bi = e1; }
#pragma unroll
            for (int off = 16; off > 0; off >>= 1) {
                float ov = __shfl_xor_sync(0xffffffffu, bv, off);
                int   oi = __shfl_xor_sync(0xffffffffu, bi, off);
                if (ov > bv || (ov == bv && oi < bi)) { bv = ov; bi = oi; }
            }
            if (t > 0) mingap = fminf(mingap, prev - bv);
            prev = bv;
            if (t < TOPK) {
                float gw0 = __shfl_sync(0xffffffffu, g0, bi & 31);
                float gw1 = __shfl_sync(0xffffffffu, g1, bi & 31);
                top_i[t] = bi;
                top_v[t] = (bi < 32) ? gw0 : gw1;
            }
            if (bi == e0) c0 = -1e30f;
            else if (bi == e1) c1 = -1e30f;
        }

        if (mingap > GAP_THETA) {
            if (lane < TOPK) {
                vals_out[lane] = top_v[lane];
                inds_out[lane] = (float)top_i[lane];
            }
            continue;
        }

        // rare near-tie token: redo ordering in fp64
        {
            double d0 = (double)gl0 + (double)nz0 * softplus_d((double)nl0);
            double d1 = (double)gl1 + (double)nz1 * softplus_d((double)nl1);
#pragma unroll
            for (int t = 0; t < TOPK; t++) {
                double bv; int bi;
                if (d0 >= d1) { bv = d0; bi = e0; } else { bv = d1; bi = e1; }
#pragma unroll
                for (int off = 16; off > 0; off >>= 1) {
                    double ov = __shfl_xor_sync(0xffffffffu, bv, off);
                    int    oi = __shfl_xor_sync(0xffffffffu, bi, off);
                    if (ov > bv || (ov == bv && oi < bi)) { bv = ov; bi = oi; }
                }
                float gw0 = __shfl_sync(0xffffffffu, g0, bi & 31);
                float gw1 = __shfl_sync(0xffffffffu, g1, bi & 31);
                if (lane == 0) {
                    vals_out[t] = (bi < 32) ? gw0 : gw1;
                    inds_out[t] = (float)bi;
                }
                if (bi == e0) d0 = -1e30;
                else if (bi == e1) d1 = -1e30;
            }
        }
    }
}

extern "C" void kernel_launch(void* const* d_in, const int* in_sizes, int n_in,
                              void* d_out, int out_size) {
    const float* hidden = (const float*)d_in[0];
    const float* Wg     = (const float*)d_in[1];
    const float* Wn     = (const float*)d_in[2];
    const float* noise  = (const float*)d_in[3];
    float* out = (float*)d_out;

    int M = in_sizes[0] / DDIM;     // 16384

    static int smem_set = 0;
    if (!smem_set) {
        cudaFuncSetAttribute(router_fused,
                             cudaFuncAttributeMaxDynamicSharedMemorySize, 49152);
        smem_set = 1;
    }

    router_fused<<<M / BM, NT, 49152>>>(hidden, Wg, Wn, noise, out, M);
}